// round 4
// baseline (speedup 1.0000x reference)
#include <cuda_runtime.h>
#include <math.h>

#define NB 4
#define Hh 64
#define Ff 10
#define Tt 60
#define Dd 6
#define Bb 2048
#define JQ 16   // j's per chunk
#define NQ 4    // chunks (quarters)

typedef unsigned long long ull;

// Packed recurrent weights: g_U4[j*64+h] = (U_i, U_ste, U_c, U_o)[j][h]
__device__ __align__(16) float4 g_U4[Hh * Hh];

__global__ void prep_kernel(const float* __restrict__ Ui, const float* __restrict__ Us,
                            const float* __restrict__ Uc, const float* __restrict__ Uo) {
    int idx = blockIdx.x * blockDim.x + threadIdx.x;
    if (idx < Hh * Hh) g_U4[idx] = make_float4(Ui[idx], Us[idx], Uc[idx], Uo[idx]);
}

__device__ __forceinline__ float hsig(float v) {
    return __saturatef(fmaf(v, 0.16666667f, 0.5f));
}
__device__ __forceinline__ ull pack2(float lo, float hi) {
    ull r; asm("mov.b64 %0, {%1, %2};" : "=l"(r) : "f"(lo), "f"(hi)); return r;
}
__device__ __forceinline__ ull fma2(ull a, ull b, ull c) {
    ull d; asm("fma.rn.f32x2 %0, %1, %2, %3;" : "=l"(d) : "l"(a), "l"(b), "l"(c)); return d;
}
__device__ __forceinline__ ull add2(ull a, ull b) {
    ull d; asm("add.rn.f32x2 %0, %1, %2;" : "=l"(d) : "l"(a), "l"(b)); return d;
}
__device__ __forceinline__ float2 unpack2(ull v) {
    float lo, hi; asm("mov.b64 {%0, %1}, %2;" : "=f"(lo), "=f"(hi) : "l"(v));
    return make_float2(lo, hi);
}
// tanh(x) = 1 - 2/(exp(2x)+1); MUFU.EX2 + MUFU.RCP, abs err ~1e-6.
__device__ __forceinline__ float ftanh(float x) {
    float e = __expf(2.0f * x);
    float r;
    asm("rcp.approx.f32 %0, %1;" : "=f"(r) : "f"(e + 1.0f));
    return fmaf(-2.0f, r, 1.0f);
}

// Block = 256 threads: h = tid&63, chunk q = tid>>6.
// Chunk q owns j-range [16q, 16q+16) (U slice in registers) and finalizes batch q.
__global__ __launch_bounds__(4 * Hh) void sfm_kernel(
    const float* __restrict__ x,
    const float* __restrict__ W_i,   const float* __restrict__ b_i,
    const float* __restrict__ W_ste, const float* __restrict__ b_ste,
    const float* __restrict__ W_fre, const float* __restrict__ U_fre, const float* __restrict__ b_fre,
    const float* __restrict__ W_c,   const float* __restrict__ b_c,
    const float* __restrict__ W_o,   const float* __restrict__ b_o,
    const float* __restrict__ U_a,   const float* __restrict__ b_a,
    const float* __restrict__ W_p,   const float* __restrict__ b_p,
    float* __restrict__ out)
{
    __shared__ float sh_x[NB * Tt * Dd];
    __shared__ __align__(16) ull sh_h[Hh][NB];            // (h,h) dup pairs
    __shared__ __align__(16) ull sh_part[NQ][NB][Hh][2];  // [chunk][batch][h][is,co]
    __shared__ float sh_frep[NQ][NB * Ff];                // per-chunk fre partials
    __shared__ float sh_fre[NB][Ff];
    __shared__ float2 sh_cssn[Tt * Ff];
    __shared__ float sh_Ufre[Hh * Ff];

    const int tid = threadIdx.x;
    const int h   = tid & (Hh - 1);
    const int q   = tid >> 6;
    const int b0  = blockIdx.x * NB;
    const int jbase = q * JQ;

    const float* xg = x + (size_t)b0 * (Tt * Dd);
    for (int i = tid; i < NB * Tt * Dd; i += 4 * Hh) sh_x[i] = xg[i];
    for (int i = tid; i < Hh * Ff; i += 4 * Hh) sh_Ufre[i] = U_fre[i];
    for (int i = tid; i < Tt * Ff; i += 4 * Hh) {
        int tt = i / Ff + 1, f = i % Ff;
        int m  = (tt * f) % Ff;
        float ang = (float)m * 0.62831853071795864769f; // 2*pi/10
        float s, c; sincosf(ang, &s, &c);
        sh_cssn[i] = make_float2(c, s);
    }
    if (q == 0) {
#pragma unroll
        for (int b = 0; b < NB; b++) sh_h[h][b] = 0ull;
    }

    // U slice into registers (64 regs): never re-read in the loop.
    ull u_is[JQ], u_co[JQ];
    {
        const ulonglong2* U2 = reinterpret_cast<const ulonglong2*>(g_U4);
#pragma unroll
        for (int jj = 0; jj < JQ; jj++) {
            ulonglong2 u = U2[(jbase + jj) * Hh + h];
            u_is[jj] = u.x; u_co[jj] = u.y;
        }
    }

    // Input weight columns + biases (seed added only by chunk q for batch q).
    ull wis[Dd], wco[Dd];
#pragma unroll
    for (int d = 0; d < Dd; d++) {
        wis[d] = pack2(W_i[d * Hh + h], W_ste[d * Hh + h]);
        wco[d] = pack2(W_c[d * Hh + h], W_o[d * Hh + h]);
    }
    const ull bias_is = pack2(b_i[h], b_ste[h]);
    const ull bias_co = pack2(b_c[h], b_o[h]);
    const float ba_ = b_a[h];
    float ua[Ff];
#pragma unroll
    for (int f = 0; f < Ff; f++) ua[f] = U_a[f];

    // fre partial duty: lanes h<40 in every chunk compute (fb,ff) over this chunk's j's.
    const bool fduty = (h < NB * Ff);
    const int  fb = h / Ff, ff = h % Ff;
    // fre owner duty: lanes h<10, finalize fre[batch q][h].
    float wf[Dd]; float bfv = 0.0f;
    if (h < Ff) {
#pragma unroll
        for (int d = 0; d < Dd; d++) wf[d] = W_fre[d * Ff + h];
        bfv = b_fre[h];
    }

    // Oscillator state for (batch q, column h).
    float sre[Ff], sim[Ff];
#pragma unroll
    for (int f = 0; f < Ff; f++) { sre[f] = 0.0f; sim[f] = 0.0f; }

    __syncthreads();

    for (int t = 0; t < Tt; t++) {
        ull acc_is[NB], acc_co[NB];
#pragma unroll
        for (int b = 0; b < NB; b++) { acc_is[b] = 0ull; acc_co[b] = 0ull; }
        {   // seed own batch with bias + x@W
            const float* xb = &sh_x[(q * Tt + t) * Dd];
            ull a0 = bias_is, a1 = bias_co;
#pragma unroll
            for (int d = 0; d < Dd; d++) {
                ull xd = pack2(xb[d], xb[d]);
                a0 = fma2(xd, wis[d], a0);
                a1 = fma2(xd, wco[d], a1);
            }
            acc_is[q] = a0; acc_co[q] = a1;
        }
        float af = 0.0f;

        // j-loop over this chunk's 16 j's — LDS broadcasts only, U in regs.
#pragma unroll
        for (int jj = 0; jj < JQ; jj++) {
            int j = jbase + jj;
            ulonglong2 q0 = *(const ulonglong2*)&sh_h[j][0];   // b0,b1
            ulonglong2 q1 = *(const ulonglong2*)&sh_h[j][2];   // b2,b3
            acc_is[0] = fma2(q0.x, u_is[jj], acc_is[0]);
            acc_co[0] = fma2(q0.x, u_co[jj], acc_co[0]);
            acc_is[1] = fma2(q0.y, u_is[jj], acc_is[1]);
            acc_co[1] = fma2(q0.y, u_co[jj], acc_co[1]);
            acc_is[2] = fma2(q1.x, u_is[jj], acc_is[2]);
            acc_co[2] = fma2(q1.x, u_co[jj], acc_co[2]);
            acc_is[3] = fma2(q1.y, u_is[jj], acc_is[3]);
            acc_co[3] = fma2(q1.y, u_co[jj], acc_co[3]);
            if (fduty) {
                float hj = ((const float*)&sh_h[j][fb])[0];
                af = fmaf(hj, sh_Ufre[j * Ff + ff], af);
            }
        }

        // Publish all 4 batch partials (incl. own — combine reads all 4).
#pragma unroll
        for (int b = 0; b < NB; b++) {
            ulonglong2 v; v.x = acc_is[b]; v.y = acc_co[b];
            *(ulonglong2*)&sh_part[q][b][h][0] = v;
        }
        if (fduty) sh_frep[q][h] = af;
        __syncthreads();  // partials + frep visible; sh_h reads done

        // Combine gate partials for owned batch q.
        ulonglong2 p0 = *(const ulonglong2*)&sh_part[0][q][h][0];
        ulonglong2 p1 = *(const ulonglong2*)&sh_part[1][q][h][0];
        ulonglong2 p2 = *(const ulonglong2*)&sh_part[2][q][h][0];
        ulonglong2 p3 = *(const ulonglong2*)&sh_part[3][q][h][0];
        ull my_is = add2(add2(p0.x, p1.x), add2(p2.x, p3.x));
        ull my_co = add2(add2(p0.y, p1.y), add2(p2.y, p3.y));

        // fre owners: finalize fre[q][h] (h<10).
        if (h < Ff) {
            const float* xb = &sh_x[(q * Tt + t) * Dd];
            float s = bfv;
#pragma unroll
            for (int d = 0; d < Dd; d++) s = fmaf(xb[d], wf[d], s);
            int idx = q * Ff + h;
            s += (sh_frep[0][idx] + sh_frep[1][idx]) + (sh_frep[2][idx] + sh_frep[3][idx]);
            sh_fre[q][h] = hsig(s);
        }
        __syncthreads();  // sh_fre visible

        // Elementwise for (batch q, column h).
        {
            float2 vis = unpack2(my_is);
            float2 vco = unpack2(my_co);
            float iv   = hsig(vis.x);
            float stev = hsig(vis.y);
            float ov   = hsig(vco.y);
            float cv   = iv * ftanh(vco.x);
            float acca = ba_;
            const float2* cssn = &sh_cssn[t * Ff];
#pragma unroll
            for (int f = 0; f < Ff; f++) {
                float fv = stev * sh_fre[q][f];
                float2 cn = cssn[f];
                float r = fmaf(fv, sre[f], cv * cn.x);
                float m = fmaf(fv, sim[f], cv * cn.y);
                sre[f] = r;
                sim[f] = m;
                acca = fmaf(fmaf(r, r, m * m), ua[f], acca);
            }
            float hv = ov * ftanh(acca);
            sh_h[h][q] = pack2(hv, hv);
        }
        __syncthreads();  // new h visible for next step
    }

    // Projection: out[b] = h @ W_p + b_p  (O = 1)
    if (tid < NB) {
        float acc = b_p[0];
#pragma unroll 8
        for (int j = 0; j < Hh; j++)
            acc = fmaf(((const float*)&sh_h[j][tid])[0], W_p[j], acc);
        out[b0 + tid] = acc;
    }
}

extern "C" void kernel_launch(void* const* d_in, const int* in_sizes, int n_in,
                              void* d_out, int out_size) {
    const float* x     = (const float*)d_in[0];
    const float* W_i   = (const float*)d_in[1];
    const float* U_i   = (const float*)d_in[2];
    const float* b_i   = (const float*)d_in[3];
    const float* W_ste = (const float*)d_in[4];
    const float* U_ste = (const float*)d_in[5];
    const float* b_ste = (const float*)d_in[6];
    const float* W_fre = (const float*)d_in[7];
    const float* U_fre = (const float*)d_in[8];
    const float* b_fre = (const float*)d_in[9];
    const float* W_c   = (const float*)d_in[10];
    const float* U_c   = (const float*)d_in[11];
    const float* b_c   = (const float*)d_in[12];
    const float* W_o   = (const float*)d_in[13];
    const float* U_o   = (const float*)d_in[14];
    const float* b_o   = (const float*)d_in[15];
    const float* U_a   = (const float*)d_in[16];
    const float* b_a   = (const float*)d_in[17];
    const float* W_p   = (const float*)d_in[18];
    const float* b_p   = (const float*)d_in[19];

    (void)in_sizes; (void)n_in; (void)out_size;

    prep_kernel<<<(Hh * Hh + 255) / 256, 256>>>(U_i, U_ste, U_c, U_o);
    sfm_kernel<<<Bb / NB, 4 * Hh>>>(x, W_i, b_i, W_ste, b_ste, W_fre, U_fre, b_fre,
                                    W_c, b_c, W_o, b_o, U_a, b_a, W_p, b_p,
                                    (float*)d_out);
}

// round 5
// speedup vs baseline: 1.2021x; 1.2021x over previous
#include <cuda_runtime.h>
#include <cuda_fp16.h>
#include <math.h>

#define NB 2
#define Hh 64
#define Ff 10
#define Tt 60
#define Dd 6
#define Bb 2048

typedef unsigned long long ull;

// fp16-packed recurrent weights: g_Uh[j*64+h] = half4 (U_i,U_ste | U_c,U_o)[j][h]
__device__ uint2 g_Uh[Hh * Hh];

__global__ void prep_kernel(const float* __restrict__ Ui, const float* __restrict__ Us,
                            const float* __restrict__ Uc, const float* __restrict__ Uo) {
    int idx = blockIdx.x * blockDim.x + threadIdx.x;
    if (idx < Hh * Hh) {
        __half2 a = __floats2half2_rn(Ui[idx], Us[idx]);
        __half2 b = __floats2half2_rn(Uc[idx], Uo[idx]);
        uint2 v;
        v.x = *reinterpret_cast<unsigned int*>(&a);
        v.y = *reinterpret_cast<unsigned int*>(&b);
        g_Uh[idx] = v;
    }
}

__device__ __forceinline__ float hsig(float v) {
    return __saturatef(fmaf(v, 0.16666667f, 0.5f));
}
__device__ __forceinline__ ull pack2(float lo, float hi) {
    ull r; asm("mov.b64 %0, {%1, %2};" : "=l"(r) : "f"(lo), "f"(hi)); return r;
}
__device__ __forceinline__ ull fma2(ull a, ull b, ull c) {
    ull d; asm("fma.rn.f32x2 %0, %1, %2, %3;" : "=l"(d) : "l"(a), "l"(b), "l"(c)); return d;
}
__device__ __forceinline__ float2 unpack2(ull v) {
    float lo, hi; asm("mov.b64 {%0, %1}, %2;" : "=f"(lo), "=f"(hi) : "l"(v));
    return make_float2(lo, hi);
}
// tanh(x) = 1 - 2/(exp(2x)+1): MUFU.EX2 + MUFU.RCP, abs err ~1e-6
__device__ __forceinline__ float ftanh(float x) {
    float e = __expf(2.0f * x);
    float r;
    asm("rcp.approx.f32 %0, %1;" : "=f"(r) : "f"(e + 1.0f));
    return fmaf(-2.0f, r, 1.0f);
}

// Block = 64 threads (thread h), NB=2 batches per block, grid = 1024.
__global__ __launch_bounds__(Hh, 7) void sfm_kernel(
    const float* __restrict__ x,
    const float* __restrict__ W_i,   const float* __restrict__ b_i,
    const float* __restrict__ W_ste, const float* __restrict__ b_ste,
    const float* __restrict__ W_fre, const float* __restrict__ U_fre, const float* __restrict__ b_fre,
    const float* __restrict__ W_c,   const float* __restrict__ b_c,
    const float* __restrict__ W_o,   const float* __restrict__ b_o,
    const float* __restrict__ U_a,   const float* __restrict__ b_a,
    const float* __restrict__ W_p,   const float* __restrict__ b_p,
    float* __restrict__ out)
{
    __shared__ __align__(16) float sh_x[NB * Tt * Dd];
    __shared__ __align__(16) ulonglong2 sh_h[Hh];     // per j: {(h,h)_b0, (h,h)_b1}
    __shared__ __align__(16) float sh_fre[NB][12];    // padded rows (48B)
    __shared__ __align__(16) float2 sh_cssn[Tt * Ff];
    __shared__ float sh_Ufre[Hh * Ff];

    const int h  = threadIdx.x;
    const int b0 = blockIdx.x * NB;

    const float* xg = x + (size_t)b0 * (Tt * Dd);
    for (int i = h; i < NB * Tt * Dd; i += Hh) sh_x[i] = xg[i];
    for (int i = h; i < Hh * Ff; i += Hh) sh_Ufre[i] = U_fre[i];
    for (int i = h; i < Tt * Ff; i += Hh) {
        int tt = i / Ff + 1, f = i % Ff;
        int m  = (tt * f) % Ff;
        float ang = (float)m * 0.62831853071795864769f; // 2*pi/10
        float s, c; sincosf(ang, &s, &c);
        sh_cssn[i] = make_float2(c, s);
    }
    sh_h[h] = make_ulonglong2(0ull, 0ull);

    // Input weight columns + biases, packed (i,ste)/(c,o).
    ull wis[Dd], wco[Dd];
#pragma unroll
    for (int d = 0; d < Dd; d++) {
        wis[d] = pack2(W_i[d * Hh + h], W_ste[d * Hh + h]);
        wco[d] = pack2(W_c[d * Hh + h], W_o[d * Hh + h]);
    }
    const ull bias_is = pack2(b_i[h], b_ste[h]);
    const ull bias_co = pack2(b_c[h], b_o[h]);
    const float ba_ = b_a[h];
    float ua[Ff];
#pragma unroll
    for (int f = 0; f < Ff; f++) ua[f] = U_a[f];

    // fre duty: lanes 0..19 (warp 0) own one (fb, ff) each.
    const bool fduty = (h < NB * Ff);
    const int  fb = h / Ff, ff = h % Ff;
    float wf[Dd]; float bfv = 0.0f;
    if (fduty) {
#pragma unroll
        for (int d = 0; d < Dd; d++) wf[d] = W_fre[d * Ff + ff];
        bfv = b_fre[ff];
    }

    // Oscillator state (batch-local, in registers): 40 regs.
    float sre[NB][Ff], sim[NB][Ff];
#pragma unroll
    for (int b = 0; b < NB; b++)
#pragma unroll
        for (int f = 0; f < Ff; f++) { sre[b][f] = 0.0f; sim[b][f] = 0.0f; }

    __syncthreads();

    for (int t = 0; t < Tt; t++) {
        // Seed with bias + x_t @ W (x via vectorized float2 broadcasts).
        ull acc_is[NB], acc_co[NB];
#pragma unroll
        for (int b = 0; b < NB; b++) {
            const float2* xb = (const float2*)&sh_x[(b * Tt + t) * Dd];
            float2 x01 = xb[0], x23 = xb[1], x45 = xb[2];
            float xv[Dd] = {x01.x, x01.y, x23.x, x23.y, x45.x, x45.y};
            ull a0 = bias_is, a1 = bias_co;
#pragma unroll
            for (int d = 0; d < Dd; d++) {
                ull xd = pack2(xv[d], xv[d]);
                a0 = fma2(xd, wis[d], a0);
                a1 = fma2(xd, wco[d], a1);
            }
            acc_is[b] = a0; acc_co[b] = a1;
        }
        float af = 0.0f;
        if (fduty) {
            const float* xb = &sh_x[(fb * Tt + t) * Dd];
            af = bfv;
#pragma unroll
            for (int d = 0; d < Dd; d++) af = fmaf(xb[d], wf[d], af);
        }

        // Recurrent matmul: fp16 U (LDG.64) + f32x2 FMAs, h via 1 LDS.128 bcast.
#pragma unroll 16
        for (int j = 0; j < Hh; j++) {
            uint2 up = g_Uh[j * Hh + h];             // LDG.64, L1-hot
            ulonglong2 hp = sh_h[j];                 // LDS.128 broadcast
            float2 f01 = __half22float2(*reinterpret_cast<__half2*>(&up.x));
            float2 f23 = __half22float2(*reinterpret_cast<__half2*>(&up.y));
            ull u_is = pack2(f01.x, f01.y);
            ull u_co = pack2(f23.x, f23.y);
            acc_is[0] = fma2(hp.x, u_is, acc_is[0]);
            acc_co[0] = fma2(hp.x, u_co, acc_co[0]);
            acc_is[1] = fma2(hp.y, u_is, acc_is[1]);
            acc_co[1] = fma2(hp.y, u_co, acc_co[1]);
            if (fduty) {
                float hj = fb ? unpack2(hp.y).x : unpack2(hp.x).x;  // reg-half select
                af = fmaf(hj, sh_Ufre[j * Ff + ff], af);
            }
        }
        if (fduty) sh_fre[fb][ff] = hsig(af);
        __syncthreads();  // fre visible; sh_h reads done

        // cssn for this t, loaded once (vectorized), shared by both batches.
        float csx[Ff], csy[Ff];
        {
            const float4* cp = (const float4*)&sh_cssn[t * Ff];
#pragma unroll
            for (int k = 0; k < 5; k++) {
                float4 v = cp[k];
                csx[2 * k] = v.x; csy[2 * k] = v.y;
                csx[2 * k + 1] = v.z; csy[2 * k + 1] = v.w;
            }
        }

        float hv[NB];
#pragma unroll
        for (int b = 0; b < NB; b++) {
            float fr[Ff];
            {
                const float4* fp = (const float4*)&sh_fre[b][0];
                float4 g0 = fp[0], g1 = fp[1];
                float2 g2 = *(const float2*)&sh_fre[b][8];
                fr[0] = g0.x; fr[1] = g0.y; fr[2] = g0.z; fr[3] = g0.w;
                fr[4] = g1.x; fr[5] = g1.y; fr[6] = g1.z; fr[7] = g1.w;
                fr[8] = g2.x; fr[9] = g2.y;
            }
            float2 vis = unpack2(acc_is[b]);
            float2 vco = unpack2(acc_co[b]);
            float iv   = hsig(vis.x);
            float stev = hsig(vis.y);
            float ov   = hsig(vco.y);
            float cv   = iv * ftanh(vco.x);
            float acca = ba_;
#pragma unroll
            for (int f = 0; f < Ff; f++) {
                float fv = stev * fr[f];
                float r = fmaf(fv, sre[b][f], cv * csx[f]);
                float m = fmaf(fv, sim[b][f], cv * csy[f]);
                sre[b][f] = r;
                sim[b][f] = m;
                acca = fmaf(fmaf(r, r, m * m), ua[f], acca);
            }
            hv[b] = ov * ftanh(acca);
        }
        sh_h[h] = make_ulonglong2(pack2(hv[0], hv[0]), pack2(hv[1], hv[1]));
        __syncthreads();  // new h visible
    }

    // Projection: out[b] = h @ W_p + b_p (O = 1)
    if (h < NB) {
        float acc = b_p[0];
        const float* hf = (const float*)&sh_h[0];
#pragma unroll 8
        for (int j = 0; j < Hh; j++)
            acc = fmaf(hf[j * 4 + h * 2], W_p[j], acc);
        out[b0 + h] = acc;
    }
}

extern "C" void kernel_launch(void* const* d_in, const int* in_sizes, int n_in,
                              void* d_out, int out_size) {
    const float* x     = (const float*)d_in[0];
    const float* W_i   = (const float*)d_in[1];
    const float* U_i   = (const float*)d_in[2];
    const float* b_i   = (const float*)d_in[3];
    const float* W_ste = (const float*)d_in[4];
    const float* U_ste = (const float*)d_in[5];
    const float* b_ste = (const float*)d_in[6];
    const float* W_fre = (const float*)d_in[7];
    const float* U_fre = (const float*)d_in[8];
    const float* b_fre = (const float*)d_in[9];
    const float* W_c   = (const float*)d_in[10];
    const float* U_c   = (const float*)d_in[11];
    const float* b_c   = (const float*)d_in[12];
    const float* W_o   = (const float*)d_in[13];
    const float* U_o   = (const float*)d_in[14];
    const float* b_o   = (const float*)d_in[15];
    const float* U_a   = (const float*)d_in[16];
    const float* b_a   = (const float*)d_in[17];
    const float* W_p   = (const float*)d_in[18];
    const float* b_p   = (const float*)d_in[19];

    (void)in_sizes; (void)n_in; (void)out_size;

    prep_kernel<<<(Hh * Hh + 255) / 256, 256>>>(U_i, U_ste, U_c, U_o);
    sfm_kernel<<<Bb / NB, Hh>>>(x, W_i, b_i, W_ste, b_ste, W_fre, U_fre, b_fre,
                                W_c, b_c, W_o, b_o, U_a, b_a, W_p, b_p,
                                (float*)d_out);
}

// round 6
// speedup vs baseline: 1.6760x; 1.3942x over previous
#include <cuda_runtime.h>
#include <cuda_bf16.h>
#include <math.h>

#define Hh 64
#define Ff 10
#define Tt 60
#define Dd 6
#define Bb 2048

typedef unsigned long long ull;

// bf16-packed recurrent weights, laid out for one LDG.128 per lane per j:
// g_Ub[j*32+lane] = { bf16x2(Ui,Us)@h=lane, bf16x2(Uc,Uo)@h=lane,
//                     bf16x2(Ui,Us)@h=lane+32, bf16x2(Uc,Uo)@h=lane+32 }
__device__ uint4 g_Ub[Hh * 32];

__device__ __forceinline__ unsigned int bpack(float a, float b) {
    __nv_bfloat162 v = __floats2bfloat162_rn(a, b);
    return *reinterpret_cast<unsigned int*>(&v);
}

__global__ void prep_kernel(const float* __restrict__ Ui, const float* __restrict__ Us,
                            const float* __restrict__ Uc, const float* __restrict__ Uo) {
    int idx = blockIdx.x * blockDim.x + threadIdx.x;   // j*32+lane
    if (idx < Hh * 32) {
        int j = idx >> 5, lane = idx & 31;
        int e0 = j * Hh + lane, e1 = j * Hh + lane + 32;
        uint4 v;
        v.x = bpack(Ui[e0], Us[e0]);
        v.y = bpack(Uc[e0], Uo[e0]);
        v.z = bpack(Ui[e1], Us[e1]);
        v.w = bpack(Uc[e1], Uo[e1]);
        g_Ub[idx] = v;
    }
}

__device__ __forceinline__ float hsig(float v) {
    return __saturatef(fmaf(v, 0.16666667f, 0.5f));
}
__device__ __forceinline__ ull pack2(float lo, float hi) {
    ull r; asm("mov.b64 %0, {%1, %2};" : "=l"(r) : "f"(lo), "f"(hi)); return r;
}
__device__ __forceinline__ ull fma2(ull a, ull b, ull c) {
    ull d; asm("fma.rn.f32x2 %0, %1, %2, %3;" : "=l"(d) : "l"(a), "l"(b), "l"(c)); return d;
}
__device__ __forceinline__ ull add2(ull a, ull b) {
    ull d; asm("add.rn.f32x2 %0, %1, %2;" : "=l"(d) : "l"(a), "l"(b)); return d;
}
__device__ __forceinline__ float2 unpack2(ull v) {
    float lo, hi; asm("mov.b64 {%0, %1}, %2;" : "=f"(lo), "=f"(hi) : "l"(v));
    return make_float2(lo, hi);
}
// bf16x2 -> two f32 via integer ops (no F2F): lo = u<<16, hi = u & 0xFFFF0000
__device__ __forceinline__ ull bf2f2(unsigned int u) {
    float lo = __uint_as_float(u << 16);
    float hi = __uint_as_float(u & 0xFFFF0000u);
    return pack2(lo, hi);
}
// tanh(x) = 1 - 2/(exp(2x)+1): MUFU.EX2 + MUFU.RCP, abs err ~1e-6
__device__ __forceinline__ float ftanh(float x) {
    float e = __expf(2.0f * x);
    float r;
    asm("rcp.approx.f32 %0, %1;" : "=f"(r) : "f"(e + 1.0f));
    return fmaf(-2.0f, r, 1.0f);
}

// Block = 64 threads = 2 INDEPENDENT warps (no barriers in the step loop).
// Warp w handles batches b0 = blockIdx*4 + 2w, b0+1.
// Lane owns h-columns {lane, lane+32} for both batches.
__global__ __launch_bounds__(64) void sfm_kernel(
    const float* __restrict__ x,
    const float* __restrict__ W_i,   const float* __restrict__ b_i,
    const float* __restrict__ W_ste, const float* __restrict__ b_ste,
    const float* __restrict__ W_fre, const float* __restrict__ U_fre, const float* __restrict__ b_fre,
    const float* __restrict__ W_c,   const float* __restrict__ b_c,
    const float* __restrict__ W_o,   const float* __restrict__ b_o,
    const float* __restrict__ U_a,   const float* __restrict__ b_a,
    const float* __restrict__ W_p,   const float* __restrict__ b_p,
    float* __restrict__ out)
{
    __shared__ __align__(8) float2 sh_xp[2][Tt][Dd];   // (x_b0, x_b1) per warp
    __shared__ __align__(8) float2 sh_cssn[Tt * Ff];
    __shared__ float sh_UfT[Ff * 65];                  // transposed, padded: [f][j]

    const int tid  = threadIdx.x;
    const int lane = tid & 31;
    const int w    = tid >> 5;
    const int b0   = blockIdx.x * 4 + w * 2;

    // ---- one-time staging (single barrier) ----
    const float* xg = x + (size_t)blockIdx.x * 4 * (Tt * Dd);
    for (int i = tid; i < 2 * Tt * Dd; i += 64) {
        int w2 = i / (Tt * Dd), r = i % (Tt * Dd);
        sh_xp[w2][r / Dd][r % Dd] =
            make_float2(xg[(2 * w2) * Tt * Dd + r], xg[(2 * w2 + 1) * Tt * Dd + r]);
    }
    for (int i = tid; i < Ff * Hh; i += 64) {
        int f = i / Hh, j = i % Hh;
        sh_UfT[f * 65 + j] = U_fre[j * Ff + f];
    }
    for (int i = tid; i < Tt * Ff; i += 64) {
        int tt = i / Ff + 1, f = i % Ff;
        int m  = (tt * f) % Ff;
        float ang = (float)m * 0.62831853071795864769f; // 2*pi/10
        float s, c; sincosf(ang, &s, &c);
        sh_cssn[i] = make_float2(c, s);
    }
    __syncthreads();   // the ONLY block barrier

    // ---- per-lane constants (registers) ----
    const int h0 = lane, h1 = lane + 32;
    ull Wg[2][2][Dd];   // [hslot][gatepair][d]
#pragma unroll
    for (int d = 0; d < Dd; d++) {
        Wg[0][0][d] = pack2(W_i[d * Hh + h0], W_ste[d * Hh + h0]);
        Wg[0][1][d] = pack2(W_c[d * Hh + h0], W_o[d * Hh + h0]);
        Wg[1][0][d] = pack2(W_i[d * Hh + h1], W_ste[d * Hh + h1]);
        Wg[1][1][d] = pack2(W_c[d * Hh + h1], W_o[d * Hh + h1]);
    }
    const ull bis[2] = { pack2(b_i[h0], b_ste[h0]), pack2(b_i[h1], b_ste[h1]) };
    const ull bco[2] = { pack2(b_c[h0], b_o[h0]),   pack2(b_c[h1], b_o[h1]) };
    const float ba_[2] = { b_a[h0], b_a[h1] };
    float ua[Ff];
#pragma unroll
    for (int f = 0; f < Ff; f++) ua[f] = U_a[f];

    // fre duty: lanes 0..19 -> (fb = lane/10, ff = lane%10)
    const bool duty = (lane < 2 * Ff);
    const int  fb = lane / Ff, ff = lane % Ff;
    float wfre[Dd];
#pragma unroll
    for (int d = 0; d < Dd; d++) wfre[d] = W_fre[d * Ff + ff];
    const float bfre = b_fre[ff];

    // Oscillator state [b][hslot][f]
    float sre[2][2][Ff], sim[2][2][Ff];
#pragma unroll
    for (int b = 0; b < 2; b++)
#pragma unroll
        for (int hs = 0; hs < 2; hs++)
#pragma unroll
            for (int f = 0; f < Ff; f++) { sre[b][hs][f] = 0.0f; sim[b][hs][f] = 0.0f; }

    // h state: hpack[hs] = (h_b0, h_b1) at column (lane + 32*hs)
    ull hpack[2] = { 0ull, 0ull };

    const uint4* Ub = g_Ub;

    for (int t = 0; t < Tt; t++) {
        // ---- seeds: bias + x_t @ W ----
        ull acc[2][2][2];   // [hslot][gatepair][b]
#pragma unroll
        for (int hs = 0; hs < 2; hs++) {
            acc[hs][0][0] = bis[hs]; acc[hs][0][1] = bis[hs];
            acc[hs][1][0] = bco[hs]; acc[hs][1][1] = bco[hs];
        }
        float xb_duty[Dd];
#pragma unroll
        for (int d = 0; d < Dd; d++) {
            float2 xv = sh_xp[w][t][d];        // LDS.64 broadcast
            ull xd0 = pack2(xv.x, xv.x);
            ull xd1 = pack2(xv.y, xv.y);
#pragma unroll
            for (int hs = 0; hs < 2; hs++) {
#pragma unroll
                for (int gp = 0; gp < 2; gp++) {
                    acc[hs][gp][0] = fma2(xd0, Wg[hs][gp][d], acc[hs][gp][0]);
                    acc[hs][gp][1] = fma2(xd1, Wg[hs][gp][d], acc[hs][gp][1]);
                }
            }
            xb_duty[d] = fb ? xv.y : xv.x;
        }
        float af = bfre;
#pragma unroll
        for (int d = 0; d < Dd; d++) af = fmaf(xb_duty[d], wfre[d], af);

        // ---- recurrent matmul: shfl h-broadcast, bf16 U, no barriers ----
#pragma unroll 8
        for (int j = 0; j < 32; j++) {
            uint4 u = Ub[j * 32 + lane];                       // LDG.128
            ull hp = __shfl_sync(0xffffffffu, hpack[0], j);    // (hb0,hb1) at column j
            float2 hbb = unpack2(hp);
            ull hd0 = pack2(hbb.x, hbb.x);
            ull hd1 = pack2(hbb.y, hbb.y);
            ull u00 = bf2f2(u.x), u01 = bf2f2(u.y);
            ull u10 = bf2f2(u.z), u11 = bf2f2(u.w);
            acc[0][0][0] = fma2(hd0, u00, acc[0][0][0]);
            acc[0][0][1] = fma2(hd1, u00, acc[0][0][1]);
            acc[0][1][0] = fma2(hd0, u01, acc[0][1][0]);
            acc[0][1][1] = fma2(hd1, u01, acc[0][1][1]);
            acc[1][0][0] = fma2(hd0, u10, acc[1][0][0]);
            acc[1][0][1] = fma2(hd1, u10, acc[1][0][1]);
            acc[1][1][0] = fma2(hd0, u11, acc[1][1][0]);
            acc[1][1][1] = fma2(hd1, u11, acc[1][1][1]);
            if (duty) af = fmaf(fb ? hbb.y : hbb.x, sh_UfT[ff * 65 + j], af);
        }
#pragma unroll 8
        for (int j = 32; j < 64; j++) {
            uint4 u = Ub[j * 32 + lane];
            ull hp = __shfl_sync(0xffffffffu, hpack[1], j - 32);
            float2 hbb = unpack2(hp);
            ull hd0 = pack2(hbb.x, hbb.x);
            ull hd1 = pack2(hbb.y, hbb.y);
            ull u00 = bf2f2(u.x), u01 = bf2f2(u.y);
            ull u10 = bf2f2(u.z), u11 = bf2f2(u.w);
            acc[0][0][0] = fma2(hd0, u00, acc[0][0][0]);
            acc[0][0][1] = fma2(hd1, u00, acc[0][0][1]);
            acc[0][1][0] = fma2(hd0, u01, acc[0][1][0]);
            acc[0][1][1] = fma2(hd1, u01, acc[0][1][1]);
            acc[1][0][0] = fma2(hd0, u10, acc[1][0][0]);
            acc[1][0][1] = fma2(hd1, u10, acc[1][0][1]);
            acc[1][1][0] = fma2(hd0, u11, acc[1][1][0]);
            acc[1][1][1] = fma2(hd1, u11, acc[1][1][1]);
            if (duty) af = fmaf(fb ? hbb.y : hbb.x, sh_UfT[ff * 65 + j], af);
        }
        const float frev = hsig(af);   // valid on duty lanes

        // ---- elementwise (warp-local; fre via shfl) ----
        float cs[Ff], sn[Ff];
#pragma unroll
        for (int f = 0; f < Ff; f++) {
            float2 cn = sh_cssn[t * Ff + f];   // LDS.64 broadcast
            cs[f] = cn.x; sn[f] = cn.y;
        }
        float hnew[2][2];   // [b][hslot]
#pragma unroll
        for (int b = 0; b < 2; b++) {
            float fre_b[Ff];
#pragma unroll
            for (int f = 0; f < Ff; f++)
                fre_b[f] = __shfl_sync(0xffffffffu, frev, b * Ff + f);
#pragma unroll
            for (int hs = 0; hs < 2; hs++) {
                float2 vis = unpack2(acc[hs][0][b]);
                float2 vco = unpack2(acc[hs][1][b]);
                float iv = hsig(vis.x);
                float sv = hsig(vis.y);
                float ov = hsig(vco.y);
                float cv = iv * ftanh(vco.x);
                float acca = ba_[hs];
#pragma unroll
                for (int f = 0; f < Ff; f++) {
                    float fv = sv * fre_b[f];
                    float r = fmaf(fv, sre[b][hs][f], cv * cs[f]);
                    float m = fmaf(fv, sim[b][hs][f], cv * sn[f]);
                    sre[b][hs][f] = r;
                    sim[b][hs][f] = m;
                    acca = fmaf(fmaf(r, r, m * m), ua[f], acca);
                }
                hnew[b][hs] = ov * ftanh(acca);
            }
        }
        hpack[0] = pack2(hnew[0][0], hnew[1][0]);
        hpack[1] = pack2(hnew[0][1], hnew[1][1]);
    }

    // ---- projection: out[b] = h @ W_p + b_p (warp butterfly reduction) ----
    {
        float wp0 = W_p[h0], wp1 = W_p[h1];
        float2 hp0 = unpack2(hpack[0]);
        float2 hp1 = unpack2(hpack[1]);
        float p_b0 = fmaf(hp0.x, wp0, hp1.x * wp1);
        float p_b1 = fmaf(hp0.y, wp0, hp1.y * wp1);
        ull pp = pack2(p_b0, p_b1);
#pragma unroll
        for (int off = 16; off >= 1; off >>= 1)
            pp = add2(pp, __shfl_xor_sync(0xffffffffu, pp, off));
        if (lane == 0) {
            float2 r = unpack2(pp);
            float bp = b_p[0];
            out[b0]     = r.x + bp;
            out[b0 + 1] = r.y + bp;
        }
    }
}

extern "C" void kernel_launch(void* const* d_in, const int* in_sizes, int n_in,
                              void* d_out, int out_size) {
    const float* x     = (const float*)d_in[0];
    const float* W_i   = (const float*)d_in[1];
    const float* U_i   = (const float*)d_in[2];
    const float* b_i   = (const float*)d_in[3];
    const float* W_ste = (const float*)d_in[4];
    const float* U_ste = (const float*)d_in[5];
    const float* b_ste = (const float*)d_in[6];
    const float* W_fre = (const float*)d_in[7];
    const float* U_fre = (const float*)d_in[8];
    const float* b_fre = (const float*)d_in[9];
    const float* W_c   = (const float*)d_in[10];
    const float* U_c   = (const float*)d_in[11];
    const float* b_c   = (const float*)d_in[12];
    const float* W_o   = (const float*)d_in[13];
    const float* U_o   = (const float*)d_in[14];
    const float* b_o   = (const float*)d_in[15];
    const float* U_a   = (const float*)d_in[16];
    const float* b_a   = (const float*)d_in[17];
    const float* W_p   = (const float*)d_in[18];
    const float* b_p   = (const float*)d_in[19];

    (void)in_sizes; (void)n_in; (void)out_size;

    prep_kernel<<<(Hh * 32 + 255) / 256, 256>>>(U_i, U_ste, U_c, U_o);
    sfm_kernel<<<Bb / 4, 64>>>(x, W_i, b_i, W_ste, b_ste, W_fre, U_fre, b_fre,
                               W_c, b_c, W_o, b_o, U_a, b_a, W_p, b_p,
                               (float*)d_out);
}

// round 7
// speedup vs baseline: 1.7186x; 1.0254x over previous
#include <cuda_runtime.h>
#include <cuda_bf16.h>
#include <math.h>

#define Hh 64
#define Ff 10
#define Tt 60
#define Dd 6
#define Bb 2048

typedef unsigned long long ull;

// Pre-DUPLICATED bf16 recurrent weights, per gate-warp:
// g_Ud[w][j*32+lane] = uint4 of bf16x2(v,v) for
//   w=0: { Ui@h=lane, Us@h=lane, Ui@h=lane+32, Us@h=lane+32 }
//   w=1: { Uc@...,    Uo@...,    Uc@...,       Uo@... }
__device__ uint4 g_Ud[2][Hh * 32];

__device__ __forceinline__ unsigned int bbdup(float v) {
    __nv_bfloat162 p = __floats2bfloat162_rn(v, v);
    return *reinterpret_cast<unsigned int*>(&p);
}

__global__ void prep_kernel(const float* __restrict__ Ui, const float* __restrict__ Us,
                            const float* __restrict__ Uc, const float* __restrict__ Uo) {
    int idx = blockIdx.x * blockDim.x + threadIdx.x;   // [0, 2*64*32)
    if (idx < 2 * Hh * 32) {
        int w = idx >> 11, r = idx & 2047;
        int j = r >> 5, lane = r & 31;
        const float* G0 = w ? Uc : Ui;
        const float* G1 = w ? Uo : Us;
        uint4 v;
        v.x = bbdup(G0[j * Hh + lane]);
        v.y = bbdup(G1[j * Hh + lane]);
        v.z = bbdup(G0[j * Hh + lane + 32]);
        v.w = bbdup(G1[j * Hh + lane + 32]);
        g_Ud[w][r] = v;
    }
}

__device__ __forceinline__ float hsig(float v) {
    return __saturatef(fmaf(v, 0.16666667f, 0.5f));
}
__device__ __forceinline__ ull pack2(float lo, float hi) {
    ull r; asm("mov.b64 %0, {%1, %2};" : "=l"(r) : "f"(lo), "f"(hi)); return r;
}
__device__ __forceinline__ ull fma2(ull a, ull b, ull c) {
    ull d; asm("fma.rn.f32x2 %0, %1, %2, %3;" : "=l"(d) : "l"(a), "l"(b), "l"(c)); return d;
}
__device__ __forceinline__ ull add2(ull a, ull b) {
    ull d; asm("add.rn.f32x2 %0, %1, %2;" : "=l"(d) : "l"(a), "l"(b)); return d;
}
__device__ __forceinline__ float2 unpack2(ull v) {
    float lo, hi; asm("mov.b64 {%0, %1}, %2;" : "=f"(lo), "=f"(hi) : "l"(v));
    return make_float2(lo, hi);
}
// (v,v) bf16x2 -> f32x2 dup pair: 2 ALU ops, no MOVs.
__device__ __forceinline__ ull bfdup2f(unsigned int u) {
    float lo = __uint_as_float(u << 16);
    float hi = __uint_as_float(u & 0xFFFF0000u);
    return pack2(lo, hi);
}
// tanh(x) = 1 - 2/(exp(2x)+1): MUFU.EX2 + MUFU.RCP, abs err ~1e-6
__device__ __forceinline__ float ftanh(float x) {
    float e = __expf(2.0f * x);
    float r;
    asm("rcp.approx.f32 %0, %1;" : "=f"(r) : "f"(e + 1.0f));
    return fmaf(-2.0f, r, 1.0f);
}

// Block = 64 threads = 2 gate-split warps sharing 4 batches.
// Warp 0 computes gates (i, ste) for all 4 batches; warp 1 computes (c, o).
// Warp w runs the elementwise tail (and fre) for batches {2w, 2w+1}.
// Lane owns h-columns {lane, lane+32}.
__global__ __launch_bounds__(64) void sfm_kernel(
    const float* __restrict__ x,
    const float* __restrict__ W_i,   const float* __restrict__ b_i,
    const float* __restrict__ W_ste, const float* __restrict__ b_ste,
    const float* __restrict__ W_fre, const float* __restrict__ U_fre, const float* __restrict__ b_fre,
    const float* __restrict__ W_c,   const float* __restrict__ b_c,
    const float* __restrict__ W_o,   const float* __restrict__ b_o,
    const float* __restrict__ U_a,   const float* __restrict__ b_a,
    const float* __restrict__ W_p,   const float* __restrict__ b_p,
    float* __restrict__ out)
{
    __shared__ __align__(16) float4 sh_x4[Tt][Dd];       // (b0,b1,b2,b3)
    __shared__ __align__(16) ulonglong2 sh_h[Hh];        // {(hb0,hb1),(hb2,hb3)} per column j
    __shared__ __align__(16) ull sh_ex[2][32][4];        // gate exchange: [writer_warp][lane][4]
    __shared__ __align__(8)  float2 sh_cssn[Tt * Ff];
    __shared__ float sh_UfT[Ff * 65];                    // transposed, padded: [f][j]

    const int tid  = threadIdx.x;
    const int lane = tid & 31;
    const int w    = tid >> 5;           // 0 = (i,ste) warp, 1 = (c,o) warp
    const int bbase = blockIdx.x * 4;

    // ---- one-time staging ----
    const float* xg = x + (size_t)bbase * (Tt * Dd);
    for (int i = tid; i < Tt * Dd; i += 64) {
        int tt = i / Dd, d = i % Dd;
        sh_x4[tt][d] = make_float4(xg[0 * Tt * Dd + i], xg[1 * Tt * Dd + i],
                                   xg[2 * Tt * Dd + i], xg[3 * Tt * Dd + i]);
    }
    for (int i = tid; i < Ff * Hh; i += 64) {
        int f = i / Hh, j = i % Hh;
        sh_UfT[f * 65 + j] = U_fre[j * Ff + f];
    }
    for (int i = tid; i < Tt * Ff; i += 64) {
        int tt = i / Ff + 1, f = i % Ff;
        int m  = (tt * f) % Ff;
        float ang = (float)m * 0.62831853071795864769f; // 2*pi/10
        float s, c; sincosf(ang, &s, &c);
        sh_cssn[i] = make_float2(c, s);
    }
    sh_h[tid] = make_ulonglong2(0ull, 0ull);

    // ---- per-lane constants ----
    const int h0 = lane, h1 = lane + 32;
    const float* Wg0 = w ? W_c : W_i;       // my gate 0
    const float* Wg1 = w ? W_o : W_ste;     // my gate 1
    const float* bg0 = w ? b_c : b_i;
    const float* bg1 = w ? b_o : b_ste;
    ull Wd[2][2][Dd];   // [gate][hslot][d], dup pairs
#pragma unroll
    for (int d = 0; d < Dd; d++) {
        Wd[0][0][d] = pack2(Wg0[d * Hh + h0], Wg0[d * Hh + h0]);
        Wd[1][0][d] = pack2(Wg1[d * Hh + h0], Wg1[d * Hh + h0]);
        Wd[0][1][d] = pack2(Wg0[d * Hh + h1], Wg0[d * Hh + h1]);
        Wd[1][1][d] = pack2(Wg1[d * Hh + h1], Wg1[d * Hh + h1]);
    }
    const ull bd[2][2] = { { pack2(bg0[h0], bg0[h0]), pack2(bg0[h1], bg0[h1]) },
                           { pack2(bg1[h0], bg1[h0]), pack2(bg1[h1], bg1[h1]) } };
    const float ba_[2] = { b_a[h0], b_a[h1] };
    float ua[Ff];
#pragma unroll
    for (int f = 0; f < Ff; f++) ua[f] = U_a[f];

    // fre duty: lanes 0..19 -> local batch fb = lane/10, freq ff = lane%10.
    const bool duty = (lane < 2 * Ff);
    const int  fb = lane / Ff, ff = lane % Ff;   // fb is RELATIVE to this warp's 2 batches
    float wfre[Dd];
#pragma unroll
    for (int d = 0; d < Dd; d++) wfre[d] = W_fre[d * Ff + ff];
    const float bfre = b_fre[ff];

    // Oscillator state for my 2 tail batches: [bl][hslot][f]
    float sre[2][2][Ff], sim[2][2][Ff];
#pragma unroll
    for (int bl = 0; bl < 2; bl++)
#pragma unroll
        for (int hs = 0; hs < 2; hs++)
#pragma unroll
            for (int f = 0; f < Ff; f++) { sre[bl][hs][f] = 0.0f; sim[bl][hs][f] = 0.0f; }

    __syncthreads();

    const uint4* Ug = &g_Ud[w][0];

    for (int t = 0; t < Tt; t++) {
        // ---- seeds: bias + x_t @ W for my 2 gates, all 4 batches ----
        // acc[gate][hslot][bp]: pair over batches (b0,b1) for bp=0, (b2,b3) for bp=1
        ull acc[2][2][2];
#pragma unroll
        for (int g = 0; g < 2; g++)
#pragma unroll
            for (int hs = 0; hs < 2; hs++) {
                acc[g][hs][0] = bd[g][hs];
                acc[g][hs][1] = bd[g][hs];
            }
        float af = bfre;
#pragma unroll
        for (int d = 0; d < Dd; d++) {
            float4 xv = sh_x4[t][d];             // LDS.128 broadcast
            ull xp0 = pack2(xv.x, xv.y);
            ull xp1 = pack2(xv.z, xv.w);
#pragma unroll
            for (int g = 0; g < 2; g++)
#pragma unroll
                for (int hs = 0; hs < 2; hs++) {
                    acc[g][hs][0] = fma2(xp0, Wd[g][hs][d], acc[g][hs][0]);
                    acc[g][hs][1] = fma2(xp1, Wd[g][hs][d], acc[g][hs][1]);
                }
            // fre x seed: component of my duty batch (w*2 + fb)
            float xd = fb ? (w ? xv.w : xv.y) : (w ? xv.z : xv.x);
            af = fmaf(xd, wfre[d], af);
        }

        // ---- recurrent matmul: pre-dup bf16 U, h pairs from shared ----
#pragma unroll 8
        for (int j = 0; j < Hh; j++) {
            uint4 u = Ug[j * 32 + lane];          // LDG.128, L1-hot (4 dup bf16x2)
            ulonglong2 hp = sh_h[j];              // LDS.128 broadcast
            ull u00 = bfdup2f(u.x);               // gate0 @h0 (dup pair)
            ull u10 = bfdup2f(u.y);               // gate1 @h0
            ull u01 = bfdup2f(u.z);               // gate0 @h1
            ull u11 = bfdup2f(u.w);               // gate1 @h1
            acc[0][0][0] = fma2(hp.x, u00, acc[0][0][0]);
            acc[0][0][1] = fma2(hp.y, u00, acc[0][0][1]);
            acc[1][0][0] = fma2(hp.x, u10, acc[1][0][0]);
            acc[1][0][1] = fma2(hp.y, u10, acc[1][0][1]);
            acc[0][1][0] = fma2(hp.x, u01, acc[0][1][0]);
            acc[0][1][1] = fma2(hp.y, u01, acc[0][1][1]);
            acc[1][1][0] = fma2(hp.x, u11, acc[1][1][0]);
            acc[1][1][1] = fma2(hp.y, u11, acc[1][1][1]);
            if (duty) {
                ull hown = w ? hp.y : hp.x;       // my warp's batch pair
                float2 hb = unpack2(hown);
                af = fmaf(fb ? hb.y : hb.x, sh_UfT[ff * 65 + j], af);
            }
        }
        const float frev = hsig(af);              // valid on duty lanes

        // ---- gate exchange: send my gates' preacts for the PEER's batch pair ----
        {
            int sbp = 1 - w;                      // peer's batch pair index
            ulonglong2* dst = reinterpret_cast<ulonglong2*>(&sh_ex[w][lane][0]);
            dst[0] = make_ulonglong2(acc[0][0][sbp], acc[1][0][sbp]);
            dst[1] = make_ulonglong2(acc[0][1][sbp], acc[1][1][sbp]);
        }
        __syncthreads();   // exchange visible; all sh_h reads of this step done
        ull p00, p10, p01, p11;                   // peer gates [gate][hslot] for MY bp
        {
            const ulonglong2* src = reinterpret_cast<const ulonglong2*>(&sh_ex[1 - w][lane][0]);
            ulonglong2 s0 = src[0], s1 = src[1];
            p00 = s0.x; p10 = s0.y; p01 = s1.x; p11 = s1.y;
        }

        // Assemble (i, ste, c, o) per hslot for my batch pair (pairs over my 2 batches).
        ull a_i[2], a_s[2], a_c[2], a_o[2];
        if (w == 0) {
#pragma unroll
            for (int hs = 0; hs < 2; hs++) { a_i[hs] = acc[0][hs][0]; a_s[hs] = acc[1][hs][0]; }
            a_c[0] = p00; a_o[0] = p10; a_c[1] = p01; a_o[1] = p11;
        } else {
#pragma unroll
            for (int hs = 0; hs < 2; hs++) { a_c[hs] = acc[0][hs][1]; a_o[hs] = acc[1][hs][1]; }
            a_i[0] = p00; a_s[0] = p10; a_i[1] = p01; a_s[1] = p11;
        }

        // ---- elementwise tail for my 2 batches (warp-local) ----
        float cs[Ff], sn[Ff];
#pragma unroll
        for (int f = 0; f < Ff; f++) {
            float2 cn = sh_cssn[t * Ff + f];
            cs[f] = cn.x; sn[f] = cn.y;
        }
        float hnew[2][2];   // [bl][hslot]
#pragma unroll
        for (int bl = 0; bl < 2; bl++) {
            float fre_b[Ff];
#pragma unroll
            for (int f = 0; f < Ff; f++)
                fre_b[f] = __shfl_sync(0xffffffffu, frev, bl * Ff + f);
#pragma unroll
            for (int hs = 0; hs < 2; hs++) {
                float2 fi = unpack2(a_i[hs]);
                float2 fs = unpack2(a_s[hs]);
                float2 fc = unpack2(a_c[hs]);
                float2 fo = unpack2(a_o[hs]);
                float iv = hsig(bl ? fi.y : fi.x);
                float sv = hsig(bl ? fs.y : fs.x);
                float ov = hsig(bl ? fo.y : fo.x);
                float cv = iv * ftanh(bl ? fc.y : fc.x);
                float acca = ba_[hs];
#pragma unroll
                for (int f = 0; f < Ff; f++) {
                    float fv = sv * fre_b[f];
                    float r = fmaf(fv, sre[bl][hs][f], cv * cs[f]);
                    float m = fmaf(fv, sim[bl][hs][f], cv * sn[f]);
                    sre[bl][hs][f] = r;
                    sim[bl][hs][f] = m;
                    acca = fmaf(fmaf(r, r, m * m), ua[f], acca);
                }
                hnew[bl][hs] = ov * ftanh(acca);
            }
        }
        // Publish my batch pair's h: column h0 and h1, my half of the ulonglong2.
        {
            ull v0 = pack2(hnew[0][0], hnew[1][0]);
            ull v1 = pack2(hnew[0][1], hnew[1][1]);
            ull* base = reinterpret_cast<ull*>(&sh_h[0]);
            base[h0 * 2 + w] = v0;
            base[h1 * 2 + w] = v1;
        }
        __syncthreads();   // new h visible for next step
    }

    // ---- projection: out[b] = h @ W_p + b_p (warp butterfly over my 2 batches) ----
    {
        float wp0 = W_p[h0], wp1 = W_p[h1];
        float pa = fmaf(
            // batch w*2 (even of my pair)
            __uint_as_float(0), 0.0f,  // placeholder keeps formatting simple
            0.0f);
        (void)pa;
        // recompute from final sh_h? No: use my hnew of last step held in regs via sh_h.
        const ull* base = reinterpret_cast<const ull*>(&sh_h[0]);
        float2 hv0 = unpack2(base[h0 * 2 + w]);   // (h_beven, h_bodd) @ h0
        float2 hv1 = unpack2(base[h1 * 2 + w]);   // @ h1
        float p_e = fmaf(hv0.x, wp0, hv1.x * wp1);
        float p_o = fmaf(hv0.y, wp0, hv1.y * wp1);
        ull pp = pack2(p_e, p_o);
#pragma unroll
        for (int off = 16; off >= 1; off >>= 1)
            pp = add2(pp, __shfl_xor_sync(0xffffffffu, pp, off));
        if (lane == 0) {
            float2 r = unpack2(pp);
            float bp = b_p[0];
            out[bbase + w * 2]     = r.x + bp;
            out[bbase + w * 2 + 1] = r.y + bp;
        }
    }
}

extern "C" void kernel_launch(void* const* d_in, const int* in_sizes, int n_in,
                              void* d_out, int out_size) {
    const float* x     = (const float*)d_in[0];
    const float* W_i   = (const float*)d_in[1];
    const float* U_i   = (const float*)d_in[2];
    const float* b_i   = (const float*)d_in[3];
    const float* W_ste = (const float*)d_in[4];
    const float* U_ste = (const float*)d_in[5];
    const float* b_ste = (const float*)d_in[6];
    const float* W_fre = (const float*)d_in[7];
    const float* U_fre = (const float*)d_in[8];
    const float* b_fre = (const float*)d_in[9];
    const float* W_c   = (const float*)d_in[10];
    const float* U_c   = (const float*)d_in[11];
    const float* b_c   = (const float*)d_in[12];
    const float* W_o   = (const float*)d_in[13];
    const float* U_o   = (const float*)d_in[14];
    const float* b_o   = (const float*)d_in[15];
    const float* U_a   = (const float*)d_in[16];
    const float* b_a   = (const float*)d_in[17];
    const float* W_p   = (const float*)d_in[18];
    const float* b_p   = (const float*)d_in[19];

    (void)in_sizes; (void)n_in; (void)out_size;

    prep_kernel<<<(2 * Hh * 32 + 255) / 256, 256>>>(U_i, U_ste, U_c, U_o);
    sfm_kernel<<<Bb / 4, 64>>>(x, W_i, b_i, W_ste, b_ste, W_fre, U_fre, b_fre,
                               W_c, b_c, W_o, b_o, U_a, b_a, W_p, b_p,
                               (float*)d_out);
}